// round 7
// baseline (speedup 1.0000x reference)
#include <cuda_runtime.h>
#include <cstdint>
#include <cstddef>

// x:   [B=8192, F=32, E=64] f32
// W:   [E=64, E=64] f32
// out: [B, P=496, E=64] f32,  out[b,p,:] = (x[b,i_p,:] @ W) * x[b,j_p,:]
// (i_p, j_p) = triu_indices(32, k=1), row-major pair order.

#define BB 8192
#define FF 32
#define EE 64
#define PP 496
#define NV4 (PP * (EE/4)) // 7936 float4 per batch row
#define NTHREADS 512
#define ROWS_PER_BLK 2

// pairs before row i: sum_{t<i} (31-t) = 31*i - i*(i-1)/2
__device__ __forceinline__ int rowstart(int i) {
    return 31 * i - (i * (i - 1)) / 2;
}

__device__ __forceinline__ float4 fmul4(float4 a, float4 c) {
    float4 r;
    r.x = a.x * c.x; r.y = a.y * c.y; r.z = a.z * c.z; r.w = a.w * c.w;
    return r;
}

// Store one batch row with 16 groups of 16 lanes (g16 in 0..15): group owns
// rows i1=g16 (31-g16 pairs) and i2=30-g16 (g16+1 pairs); g16==15 owns only
// row 15. Inner body: 1 LDS.128 + 1 STG.128; 256B-contiguous group stores.
__device__ __forceinline__ void store_rows(const float4* __restrict__ xw4,
                                           const float4* __restrict__ xs4,
                                           float4* __restrict__ og,
                                           int g16, int v)
{
    {
        const int i = g16;
        const float4 a = xw4[i * 16 + v];
        float4* o = og + (ptrdiff_t)(rowstart(i) - i - 1) * 16 + v;
        #pragma unroll 4
        for (int j = i + 1; j < FF; ++j)
            __stcs(o + j * 16, fmul4(a, xs4[j * 16 + v]));
    }
    if (g16 < 15) {
        const int i = 30 - g16;
        const float4 a = xw4[i * 16 + v];
        float4* o = og + (ptrdiff_t)(rowstart(i) - i - 1) * 16 + v;
        #pragma unroll 4
        for (int j = i + 1; j < FF; ++j)
            __stcs(o + j * 16, fmul4(a, xs4[j * 16 + v]));
    }
}

__global__ __launch_bounds__(NTHREADS)
void bilinear_kernel(const float* __restrict__ x,
                     const float* __restrict__ W,
                     float* __restrict__ out)
{
    // 32 KB total: W region is dead after the matmul and is reused for the
    // two xw tiles (2 x 8 KB).
    __shared__ float xs[ROWS_PER_BLK * FF * EE]; // 16 KB : x[b0], x[b0+1]
    __shared__ float wsxw[EE * EE];              // 16 KB : W, then xw[0],xw[1]

    const int tid = threadIdx.x;
    const int b0  = blockIdx.x * ROWS_PER_BLK;

    // ---- load x rows (1024 float4) and W (1024 float4) into SMEM ----
    {
        const float4* xg = reinterpret_cast<const float4*>(x) + (size_t)b0 * (FF * EE / 4);
        float4* xs4 = reinterpret_cast<float4*>(xs);
        #pragma unroll
        for (int q = tid; q < ROWS_PER_BLK * FF * EE / 4; q += NTHREADS)
            xs4[q] = xg[q];

        const float4* wg = reinterpret_cast<const float4*>(W);
        float4* ws4 = reinterpret_cast<float4*>(wsxw);
        #pragma unroll
        for (int q = tid; q < EE * EE / 4; q += NTHREADS)
            ws4[q] = wg[q];
    }

    __syncthreads();

    // ---- matmul: xw[r][f][e] = sum_k xs[r][f][k] * W[k][e] ----
    // 512 threads: 1 f-row x 4 e-cols x 2 batch rows each (8 acc floats).
    const int e0 = (tid & 15) * 4;
    const int f  = tid >> 4;           // 0..31
    {
        float4 a0 = make_float4(0.f, 0.f, 0.f, 0.f);
        float4 a1 = make_float4(0.f, 0.f, 0.f, 0.f);

        const float* xr0 = xs +            f * EE;
        const float* xr1 = xs + FF * EE +  f * EE;

        #pragma unroll 8
        for (int k = 0; k < EE; ++k) {
            const float4 w = *reinterpret_cast<const float4*>(&wsxw[k * EE + e0]);
            const float x0 = xr0[k];
            const float x1 = xr1[k];
            a0.x += x0 * w.x; a0.y += x0 * w.y; a0.z += x0 * w.z; a0.w += x0 * w.w;
            a1.x += x1 * w.x; a1.y += x1 * w.y; a1.z += x1 * w.z; a1.w += x1 * w.w;
        }

        __syncthreads();  // all ws reads done before overwriting with xw

        *reinterpret_cast<float4*>(&wsxw[          f * EE + e0]) = a0;
        *reinterpret_cast<float4*>(&wsxw[FF * EE + f * EE + e0]) = a1;
    }

    __syncthreads();

    // ---- store phase ----
    // 32 groups of 16 lanes: groups 0..15 -> batch row 0, 16..31 -> batch row 1.
    {
        const int v   = tid & 15;
        const int g   = tid >> 4;       // 0..31
        const int r   = g >> 4;         // batch row select
        const int g16 = g & 15;

        float4* og = reinterpret_cast<float4*>(out) + (size_t)(b0 + r) * NV4;

        store_rows(reinterpret_cast<const float4*>(wsxw + r * FF * EE),
                   reinterpret_cast<const float4*>(xs   + r * FF * EE),
                   og, g16, v);
    }
}

extern "C" void kernel_launch(void* const* d_in, const int* in_sizes, int n_in,
                              void* d_out, int out_size)
{
    const float* x = (const float*)d_in[0]; // [8192, 32, 64]
    const float* W = (const float*)d_in[1]; // [64, 64]
    float* out = (float*)d_out;             // [8192, 496, 64]
    (void)in_sizes; (void)n_in; (void)out_size;

    bilinear_kernel<<<BB / ROWS_PER_BLK, NTHREADS>>>(x, W, out);
}

// round 8
// speedup vs baseline: 1.0013x; 1.0013x over previous
#include <cuda_runtime.h>
#include <cstdint>
#include <cstddef>

// x:   [B=8192, F=32, E=64] f32
// W:   [E=64, E=64] f32
// out: [B, P=496, E=64] f32,  out[b,p,:] = (x[b,i_p,:] @ W) * x[b,j_p,:]
// (i_p, j_p) = triu_indices(32, k=1), row-major pair order.

#define BB 8192
#define FF 32
#define EE 64
#define PP 496
#define NV4 (PP * (EE/4)) // 7936 float4 per batch row
#define NTHREADS 512
#define ROWS_PER_BLK 2

// pairs before row i: sum_{t<i} (31-t) = 31*i - i*(i-1)/2
__device__ __forceinline__ int rowstart(int i) {
    return 31 * i - (i * (i - 1)) / 2;
}

__device__ __forceinline__ float4 fmul4(float4 a, float4 c) {
    float4 r;
    r.x = a.x * c.x; r.y = a.y * c.y; r.z = a.z * c.z; r.w = a.w * c.w;
    return r;
}

// Store one batch row with 16 groups of 16 lanes (g16 in 0..15): group owns
// rows i1=g16 (31-g16 pairs) and i2=30-g16 (g16+1 pairs); g16==15 owns only
// row 15. Inner body: 1 LDS.128 + 1 STG.128; group writes are sequential
// 256B chunks (8KB/row region) -> ideal for L2 write aggregation.
__device__ __forceinline__ void store_rows(const float4* __restrict__ xw4,
                                           const float4* __restrict__ xs4,
                                           float4* __restrict__ og,
                                           int g16, int v)
{
    {
        const int i = g16;
        const float4 a = xw4[i * 16 + v];
        float4* o = og + (ptrdiff_t)(rowstart(i) - i - 1) * 16 + v;
        #pragma unroll 4
        for (int j = i + 1; j < FF; ++j)
            o[j * 16] = fmul4(a, xs4[j * 16 + v]);   // plain write-back STG (A/B vs __stcs)
    }
    if (g16 < 15) {
        const int i = 30 - g16;
        const float4 a = xw4[i * 16 + v];
        float4* o = og + (ptrdiff_t)(rowstart(i) - i - 1) * 16 + v;
        #pragma unroll 4
        for (int j = i + 1; j < FF; ++j)
            o[j * 16] = fmul4(a, xs4[j * 16 + v]);
    }
}

__global__ __launch_bounds__(NTHREADS)
void bilinear_kernel(const float* __restrict__ x,
                     const float* __restrict__ W,
                     float* __restrict__ out)
{
    // 32 KB total: W region is dead after the matmul and is reused for the
    // two xw tiles (2 x 8 KB).
    __shared__ float xs[ROWS_PER_BLK * FF * EE]; // 16 KB : x[b0], x[b0+1]
    __shared__ float wsxw[EE * EE];              // 16 KB : W, then xw[0],xw[1]

    const int tid = threadIdx.x;
    const int b0  = blockIdx.x * ROWS_PER_BLK;

    // ---- load x rows (1024 float4) and W (1024 float4) into SMEM ----
    {
        const float4* xg = reinterpret_cast<const float4*>(x) + (size_t)b0 * (FF * EE / 4);
        float4* xs4 = reinterpret_cast<float4*>(xs);
        #pragma unroll
        for (int q = tid; q < ROWS_PER_BLK * FF * EE / 4; q += NTHREADS)
            xs4[q] = xg[q];

        const float4* wg = reinterpret_cast<const float4*>(W);
        float4* ws4 = reinterpret_cast<float4*>(wsxw);
        #pragma unroll
        for (int q = tid; q < EE * EE / 4; q += NTHREADS)
            ws4[q] = wg[q];
    }

    __syncthreads();

    // ---- matmul: xw[r][f][e] = sum_k xs[r][f][k] * W[k][e] ----
    // 512 threads: 1 f-row x 4 e-cols x 2 batch rows each (8 acc floats).
    const int e0 = (tid & 15) * 4;
    const int f  = tid >> 4;           // 0..31
    {
        float4 a0 = make_float4(0.f, 0.f, 0.f, 0.f);
        float4 a1 = make_float4(0.f, 0.f, 0.f, 0.f);

        const float* xr0 = xs +            f * EE;
        const float* xr1 = xs + FF * EE +  f * EE;

        #pragma unroll 8
        for (int k = 0; k < EE; ++k) {
            const float4 w = *reinterpret_cast<const float4*>(&wsxw[k * EE + e0]);
            const float x0 = xr0[k];
            const float x1 = xr1[k];
            a0.x += x0 * w.x; a0.y += x0 * w.y; a0.z += x0 * w.z; a0.w += x0 * w.w;
            a1.x += x1 * w.x; a1.y += x1 * w.y; a1.z += x1 * w.z; a1.w += x1 * w.w;
        }

        __syncthreads();  // all ws reads done before overwriting with xw

        *reinterpret_cast<float4*>(&wsxw[          f * EE + e0]) = a0;
        *reinterpret_cast<float4*>(&wsxw[FF * EE + f * EE + e0]) = a1;
    }

    __syncthreads();

    // ---- store phase ----
    // 32 groups of 16 lanes: groups 0..15 -> batch row 0, 16..31 -> batch row 1.
    {
        const int v   = tid & 15;
        const int g   = tid >> 4;       // 0..31
        const int r   = g >> 4;         // batch row select
        const int g16 = g & 15;

        float4* og = reinterpret_cast<float4*>(out) + (size_t)(b0 + r) * NV4;

        store_rows(reinterpret_cast<const float4*>(wsxw + r * FF * EE),
                   reinterpret_cast<const float4*>(xs   + r * FF * EE),
                   og, g16, v);
    }
}

extern "C" void kernel_launch(void* const* d_in, const int* in_sizes, int n_in,
                              void* d_out, int out_size)
{
    const float* x = (const float*)d_in[0]; // [8192, 32, 64]
    const float* W = (const float*)d_in[1]; // [64, 64]
    float* out = (float*)d_out;             // [8192, 496, 64]
    (void)in_sizes; (void)n_in; (void)out_size;

    bilinear_kernel<<<BB / ROWS_PER_BLK, NTHREADS>>>(x, W, out);
}